// round 14
// baseline (speedup 1.0000x reference)
#include <cuda_runtime.h>
#include <cuda_bf16.h>
#include <cstdint>

#define T 1024
#define BATCH 64
#define NGEMM 192           // 3 branches * 16 tile-pairs * 4 b-quarters
#define AESZ 1112           // u16 entries per ext array (idx = 32 + (k-i))
#define AEPAD 1120          // padded stride (16B multiple)

// ---------------- device scratch (no allocations allowed) ----------------
__device__ uint2 d_g[3][BATCH][T / 2];          // (hi_word, lo_word) per k-pair
__device__ unsigned short d_ae[3][4][AEPAD];    // [0]=h0 [1]=l0 [2]=h1 [3]=l1
__device__ float d_tail[3][T];                  // (1-ba) + sig(-10)*suffix
__device__ float d_a2sm[3][T];                  // softmax(A2)
__device__ float d_Spart[3][16][BATCH];
__device__ int   d_ctr;

__device__ __forceinline__ float clamp01(float v) { return fminf(fmaxf(v, 0.f), 1.f); }
__device__ __forceinline__ unsigned short f2bf(float f) {
    return __bfloat16_as_ushort(__float2bfloat16(f));
}
__device__ __forceinline__ float bf2f(unsigned short u) {
    return __bfloat162float(__ushort_as_bfloat16(u));
}

// m16n8k16 bf16 HMMA, fp32 accum in place. Not volatile (pure-register asm).
__device__ __forceinline__ void hmma(float* d, uint32_t a0, uint32_t a1,
                                     uint32_t a2, uint32_t a3,
                                     uint32_t b0, uint32_t b1) {
    asm("mma.sync.aligned.m16n8k16.row.col.f32.bf16.bf16.f32 "
        "{%0,%1,%2,%3}, {%4,%5,%6,%7}, {%8,%9}, {%0,%1,%2,%3};"
        : "+f"(d[0]), "+f"(d[1]), "+f"(d[2]), "+f"(d[3])
        : "r"(a0), "r"(a1), "r"(a2), "r"(a3), "r"(b0), "r"(b1));
}

// ---------------------------------------------------------------------------
// Setup kernel: 99 blocks x 1024 threads.
//   blocks 0..95:  sigmoid rows -> interleaved bf16 hi/lo (2 rows per block)
//   blocks 96..98: per-branch softmax(A1)+suffix->tail, split arrays, softmax(A2)
// ---------------------------------------------------------------------------
__global__ void __launch_bounds__(1024) setup_kernel(
    const float* __restrict__ x1, const float* __restrict__ x2, const float* __restrict__ x3,
    const float* __restrict__ t1p, const float* __restrict__ b1p,
    const float* __restrict__ t2p, const float* __restrict__ b2p,
    const float* __restrict__ t3p, const float* __restrict__ b3p,
    const float* __restrict__ A1a, const float* __restrict__ A1b, const float* __restrict__ A1c,
    const float* __restrict__ A2a, const float* __restrict__ A2b, const float* __restrict__ A2c,
    const float* __restrict__ ba1, const float* __restrict__ ba2, const float* __restrict__ ba3)
{
    int bid = blockIdx.x;
    int t = threadIdx.x;

    if (bid < 96) {
        // ---- sigmoid splits: branch br, rows 2*pr, 2*pr+1 ----
        int br = bid / 32;
        int pr = bid % 32;
        const float* xs = (br == 0) ? x1 : (br == 1) ? x2 : x3;
        const float* tp = (br == 0) ? t1p : (br == 1) ? t2p : t3p;
        const float* bp = (br == 0) ? b1p : (br == 1) ? b2p : b3p;
        float tv = tp[0], bv = bp[0];

        int row = 2 * pr + (t >> 9);
        int m = t & 511;                  // k-pair index (k = 2m, 2m+1)
        const float* xr = xs + row * T;
        float2 xv = *(const float2*)(xr + 2 * m);
        unsigned short h2[2], l2[2];
        float xin[2] = {xv.x, xv.y};
        #pragma unroll
        for (int e = 0; e < 2; e++) {
            float prod = __fmul_rn(xin[e], tv);   // no contraction: exact r==b test
            float r = __fsub_rn(bv, prod);
            if (r == bv) r = -10.f;
            float g = __fdividef(1.f, 1.f + __expf(-r));
            h2[e] = f2bf(g);
            l2[e] = f2bf(g - bf2f(h2[e]));
        }
        uint2 o;
        o.x = (uint32_t)h2[0] | ((uint32_t)h2[1] << 16);
        o.y = (uint32_t)l2[0] | ((uint32_t)l2[1] << 16);
        d_g[br][row][m] = o;
        return;
    }

    // ---- per-branch softmax block (1024 threads, 1 element each) ----
    __shared__ float sAf[1024];
    __shared__ float sh[1024];
    __shared__ float sh32[32];
    __shared__ float swoff[32];
    int br = bid - 96;
    const float* A1 = (br == 0) ? A1a : (br == 1) ? A1b : A1c;
    const float* A2 = (br == 0) ? A2a : (br == 1) ? A2b : A2c;
    const float* bap = (br == 0) ? ba1 : (br == 1) ? ba2 : ba3;
    const float SIG10 = 4.5397868702434395e-05f;
    int w = t >> 5, l = t & 31;

    // softmax(A1)
    float v = A1[t];
    float m1 = v;
    #pragma unroll
    for (int off = 16; off; off >>= 1) m1 = fmaxf(m1, __shfl_xor_sync(0xffffffffu, m1, off));
    if (l == 0) sh32[w] = m1;
    __syncthreads();
    if (w == 0) {
        float x = sh32[l];
        #pragma unroll
        for (int off = 16; off; off >>= 1) x = fmaxf(x, __shfl_xor_sync(0xffffffffu, x, off));
        if (l == 0) sh32[0] = x;
    }
    __syncthreads();
    float M = sh32[0];
    __syncthreads();
    float e = __expf(v - M);
    float s1 = e;
    #pragma unroll
    for (int off = 16; off; off >>= 1) s1 += __shfl_xor_sync(0xffffffffu, s1, off);
    if (l == 0) sh32[w] = s1;
    __syncthreads();
    if (w == 0) {
        float x = sh32[l];
        #pragma unroll
        for (int off = 16; off; off >>= 1) x += __shfl_xor_sync(0xffffffffu, x, off);
        if (l == 0) sh32[0] = x;
    }
    __syncthreads();
    float a1 = e * __fdividef(1.f, sh32[0]);
    sAf[t] = a1;
    __syncthreads();

    // inclusive suffix scan of a1 (verified R1 pattern)
    float s = a1;
    #pragma unroll
    for (int off = 1; off < 32; off <<= 1) {
        float o = __shfl_down_sync(0xffffffffu, s, off);
        if (l + off < 32) s += o;
    }
    if (l == 0) sh32[w] = s;
    __syncthreads();
    if (w == 0) {
        float x = sh32[l];
        float inc = x;
        #pragma unroll
        for (int off = 1; off < 32; off <<= 1) {
            float o = __shfl_down_sync(0xffffffffu, inc, off);
            if (l + off < 32) inc += o;
        }
        float excl = __shfl_down_sync(0xffffffffu, inc, 1);
        if (l == 31) excl = 0.f;
        swoff[l] = excl;
    }
    __syncthreads();
    float Ssuf_t = s + swoff[w];
    sh[t] = Ssuf_t;
    __syncthreads();
    float ba = bap[0];
    float ssuf_for_i = (t == 0) ? 0.f : sh[1024 - t];
    d_tail[br][t] = (1.f - ba) + SIG10 * ssuf_for_i;
    __syncthreads();

    // split ext arrays (x = t, and x = 1024 + t for t < AESZ-1024)
    for (int x = t; x < AESZ; x += 1024) {
        float v0 = (x >= 32 && x < 1056) ? sAf[x - 32] : 0.f;
        float v1 = (x + 1 >= 32 && x + 1 < 1056) ? sAf[x - 31] : 0.f;
        unsigned short h0 = f2bf(v0);
        unsigned short h1 = f2bf(v1);
        d_ae[br][0][x] = h0;
        d_ae[br][1][x] = f2bf(v0 - bf2f(h0));
        d_ae[br][2][x] = h1;
        d_ae[br][3][x] = f2bf(v1 - bf2f(h1));
    }
    if (t < AEPAD - AESZ) {
        #pragma unroll
        for (int a = 0; a < 4; a++) d_ae[br][a][AESZ + t] = 0;
    }

    // softmax(A2)
    float v2 = A2[t];
    float m2 = v2;
    #pragma unroll
    for (int off = 16; off; off >>= 1) m2 = fmaxf(m2, __shfl_xor_sync(0xffffffffu, m2, off));
    if (l == 0) sh32[w] = m2;
    __syncthreads();
    if (w == 0) {
        float x = sh32[l];
        #pragma unroll
        for (int off = 16; off; off >>= 1) x = fmaxf(x, __shfl_xor_sync(0xffffffffu, x, off));
        if (l == 0) sh32[0] = x;
    }
    __syncthreads();
    float M2 = sh32[0];
    __syncthreads();
    float e2 = __expf(v2 - M2);
    float s2 = e2;
    #pragma unroll
    for (int off = 16; off; off >>= 1) s2 += __shfl_xor_sync(0xffffffffu, s2, off);
    if (l == 0) sh32[w] = s2;
    __syncthreads();
    if (w == 0) {
        float x = sh32[l];
        #pragma unroll
        for (int off = 16; off; off >>= 1) x += __shfl_xor_sync(0xffffffffu, x, off);
        if (l == 0) sh32[0] = x;
    }
    __syncthreads();
    d_a2sm[br][t] = e2 * __fdividef(1.f, sh32[0]);
}

// ---------------------------------------------------------------------------
// GEMM kernel: 192 CTAs x 512 threads, 2 CTAs/SM. CTA = (br, pair tp, bq).
// Preamble = one gmem->smem copy of the 4 split arrays. Merge = 1 barrier.
// ---------------------------------------------------------------------------
__global__ void __launch_bounds__(512, 2) gemm_kernel(
    const float* __restrict__ bb1, const float* __restrict__ bb2, const float* __restrict__ bb3,
    const float* __restrict__ A4, const float* __restrict__ beta4p,
    float* __restrict__ out)
{
    __shared__ __align__(16) unsigned short sAe[4][AEPAD];   // h0,l0,h1,l1
    __shared__ __align__(16) float sDp[8][2][32][18];
    __shared__ float sBlk[512];
    __shared__ int sDone;

    int bid = blockIdx.x;
    int br = bid >> 6;                 // 0..2
    int rem = bid & 63;
    int tp = rem >> 2;                 // pair 0..15
    int bq = rem & 3;                  // b-quarter (16 cols)
    int I0A = 32 * tp;
    int I0B = 32 * (31 - tp);
    int nk  = 64 - 2 * tp;             // k-steps from I0A to 1024
    int ksB = 2 * (31 - 2 * tp);       // first k-step overlapping tile B

    int t = threadIdx.x;
    int w = t >> 5, l = t & 31;
    int roff = l >> 2;                 // fragment row offset 0..7
    int cq = l & 3;                    // fragment k-pair 0..3
    int colg = w & 1;                  // col group (8 b each)
    int kpar = w >> 1;                 // k parity 0..7

    // ---- preamble: copy 4 split arrays (8960 B) gmem -> smem ----
    {
        const uint4* src = (const uint4*)&d_ae[br][0][0];
        uint4* dst = (uint4*)&sAe[0][0];
        const int NV = 4 * AEPAD * 2 / 16;   // 560
        for (int i = t; i < NV; i += 512) dst[i] = __ldg(src + i);
    }
    __syncthreads();

    // ---- main K loop (warp handles ks = kpar, kpar+8, ...) ----
    const uint32_t* Ah = (const uint32_t*)((roff & 1) ? sAe[2] : sAe[0]);
    const uint32_t* Al = (const uint32_t*)((roff & 1) ? sAe[3] : sAe[1]);
    int Pc = 32 + 2 * cq - roff;       // thread-constant base (u16 units)

    int n = bq * 16 + 8 * colg + roff;
    const uint2* gn = &d_g[br][n][0];

    float accA0[4] = {0, 0, 0, 0}, accA1[4] = {0, 0, 0, 0};
    float accB0[4] = {0, 0, 0, 0}, accB1[4] = {0, 0, 0, 0};

    uint2 bqr[2][2];
    {
        int k0 = kpar;
        int k1 = (kpar + 8 < nk) ? (kpar + 8) : kpar;
        int kw0 = ((I0A + 16 * k0) >> 1) + cq;
        int kw1 = ((I0A + 16 * k1) >> 1) + cq;
        bqr[0][0] = __ldg(gn + kw0); bqr[0][1] = __ldg(gn + kw0 + 4);
        bqr[1][0] = __ldg(gn + kw1); bqr[1][1] = __ldg(gn + kw1 + 4);
    }

    int it = 0;
    for (int ks = kpar; ks < nk; ks += 8, it++) {
        uint32_t bh0 = bqr[it & 1][0].x, bl0 = bqr[it & 1][0].y;
        uint32_t bh1 = bqr[it & 1][1].x, bl1 = bqr[it & 1][1].y;
        if (ks + 16 < nk) {
            int kw = ((I0A + 16 * (ks + 16)) >> 1) + cq;
            bqr[it & 1][0] = __ldg(gn + kw);
            bqr[it & 1][1] = __ldg(gn + kw + 4);
        }

        int Q0 = (Pc + 16 * ks) >> 1;
        uint32_t uhA0 = Ah[Q0 - 12], uhA1 = Ah[Q0 - 8], uhA2 = Ah[Q0 - 4];
        uint32_t uhA3 = Ah[Q0],      uhA4 = Ah[Q0 + 4];
        uint32_t ulA0 = Al[Q0 - 12], ulA1 = Al[Q0 - 8], ulA2 = Al[Q0 - 4];
        uint32_t ulA3 = Al[Q0],      ulA4 = Al[Q0 + 4];

        if (ks >= ksB) {
            int QB = (Pc + 16 * (ks - ksB)) >> 1;
            uint32_t uhB0 = Ah[QB - 12], uhB1 = Ah[QB - 8], uhB2 = Ah[QB - 4];
            uint32_t uhB3 = Ah[QB],      uhB4 = Ah[QB + 4];
            uint32_t ulB0 = Al[QB - 12], ulB1 = Al[QB - 8], ulB2 = Al[QB - 4];
            uint32_t ulB3 = Al[QB],      ulB4 = Al[QB + 4];
            hmma(accA0, uhA3, uhA2, uhA4, uhA3, bh0, bh1);
            hmma(accA1, uhA1, uhA0, uhA2, uhA1, bh0, bh1);
            hmma(accB0, uhB3, uhB2, uhB4, uhB3, bh0, bh1);
            hmma(accB1, uhB1, uhB0, uhB2, uhB1, bh0, bh1);
            hmma(accA0, uhA3, uhA2, uhA4, uhA3, bl0, bl1);
            hmma(accA1, uhA1, uhA0, uhA2, uhA1, bl0, bl1);
            hmma(accB0, uhB3, uhB2, uhB4, uhB3, bl0, bl1);
            hmma(accB1, uhB1, uhB0, uhB2, uhB1, bl0, bl1);
            hmma(accA0, ulA3, ulA2, ulA4, ulA3, bh0, bh1);
            hmma(accA1, ulA1, ulA0, ulA2, ulA1, bh0, bh1);
            hmma(accB0, ulB3, ulB2, ulB4, ulB3, bh0, bh1);
            hmma(accB1, ulB1, ulB0, ulB2, ulB1, bh0, bh1);
        } else {
            hmma(accA0, uhA3, uhA2, uhA4, uhA3, bh0, bh1);
            hmma(accA1, uhA1, uhA0, uhA2, uhA1, bh0, bh1);
            hmma(accA0, uhA3, uhA2, uhA4, uhA3, bl0, bl1);
            hmma(accA1, uhA1, uhA0, uhA2, uhA1, bl0, bl1);
            hmma(accA0, ulA3, ulA2, ulA4, ulA3, bh0, bh1);
            hmma(accA1, ulA1, ulA0, ulA2, ulA1, bh0, bh1);
        }
    }

    // ---- store per-parity partials; single barrier ----
    {
        int c0 = 8 * colg + 2 * cq;
        float (*dst)[32][18] = sDp[kpar];
        dst[0][roff +  0][c0] = accA0[0]; dst[0][roff +  0][c0 + 1] = accA0[1];
        dst[0][roff +  8][c0] = accA0[2]; dst[0][roff +  8][c0 + 1] = accA0[3];
        dst[0][roff + 16][c0] = accA1[0]; dst[0][roff + 16][c0 + 1] = accA1[1];
        dst[0][roff + 24][c0] = accA1[2]; dst[0][roff + 24][c0 + 1] = accA1[3];
        dst[1][roff +  0][c0] = accB0[0]; dst[1][roff +  0][c0 + 1] = accB0[1];
        dst[1][roff +  8][c0] = accB0[2]; dst[1][roff +  8][c0 + 1] = accB0[3];
        dst[1][roff + 16][c0] = accB1[0]; dst[1][roff + 16][c0 + 1] = accB1[1];
        dst[1][roff + 24][c0] = accB1[2]; dst[1][roff + 24][c0 + 1] = accB1[3];
    }
    __syncthreads();

    // ---- epilogue: sum 8 parities, tail, clip, A2-weight, per-b reduce ----
    {
        int b = t & 15;                // local b column 0..15
        int grp = t >> 4;              // 0..31, each handles 2 of 64 rows
        float local = 0.f;
        #pragma unroll
        for (int rr = 0; rr < 2; rr++) {
            int idx = grp * 2 + rr;    // 0..63
            int tile = idx >> 5;
            int row = idx & 31;
            int i = (tile ? I0B : I0A) + row;
            float v = 0.f;
            #pragma unroll
            for (int p = 0; p < 8; p++) v += sDp[p][tile][row][b];
            float wb1 = v + __ldg(&d_tail[br][i]);
            local += __ldg(&d_a2sm[br][i]) * (1.f - clamp01(wb1));
        }
        sBlk[t] = local;
    }
    __syncthreads();
    if (t < 16) {
        float S = 0.f;
        #pragma unroll
        for (int g = 0; g < 32; g++) S += sBlk[t + 16 * g];
        d_Spart[br][tp][bq * 16 + t] = S;
    }

    // ---- last-CTA final combine ----
    __threadfence();
    if (t == 0) {
        int v = atomicAdd(&d_ctr, 1);
        sDone = (v == NGEMM - 1) ? 1 : 0;
    }
    __syncthreads();
    if (sDone) {
        if (t < BATCH) {
            float e0 = __expf(A4[0]), e1 = __expf(A4[1]), e2 = __expf(A4[2]);
            float sinv = __fdividef(1.f, e0 + e1 + e2);
            float a40 = e0 * sinv, a41 = e1 * sinv, a42 = e2 * sinv;
            volatile float* vs = (volatile float*)d_Spart;   // [3][16][64]
            float Sb[3];
            #pragma unroll
            for (int r = 0; r < 3; r++) {
                float acc = 0.f;
                #pragma unroll
                for (int p = 0; p < 16; p++) acc += vs[(r * 16 + p) * 64 + t];
                Sb[r] = acc;
            }
            float r0 = clamp01(bb1[0] - Sb[0]);
            float r1 = clamp01(bb2[0] - Sb[1]);
            float r2 = clamp01(bb3[0] - Sb[2]);
            float acc4 = beta4p[0];
            acc4 -= a40 * (1.f - r0);
            acc4 -= a41 * (1.f - r1);
            acc4 -= a42 * (1.f - r2);
            out[t] = clamp01(acc4);
        }
        if (t == 0) d_ctr = 0;
    }
}

extern "C" void kernel_launch(void* const* d_in, const int* in_sizes, int n_in,
                              void* d_out, int out_size)
{
    const float* x1      = (const float*)d_in[0];
    const float* x2      = (const float*)d_in[1];
    const float* x3      = (const float*)d_in[2];
    const float* t1      = (const float*)d_in[3];
    const float* b1      = (const float*)d_in[4];
    const float* A1_1    = (const float*)d_in[5];
    const float* A2_1    = (const float*)d_in[6];
    const float* beta1_1 = (const float*)d_in[7];
    const float* beta1_2 = (const float*)d_in[8];
    const float* t2      = (const float*)d_in[9];
    const float* b2      = (const float*)d_in[10];
    const float* A1_2    = (const float*)d_in[11];
    const float* A2_2    = (const float*)d_in[12];
    const float* beta2_1 = (const float*)d_in[13];
    const float* beta2_2 = (const float*)d_in[14];
    const float* t3      = (const float*)d_in[15];
    const float* b3      = (const float*)d_in[16];
    const float* A1_3    = (const float*)d_in[17];
    const float* A2_3    = (const float*)d_in[18];
    const float* beta3_1 = (const float*)d_in[19];
    const float* beta3_2 = (const float*)d_in[20];
    const float* A4      = (const float*)d_in[21];
    const float* beta4   = (const float*)d_in[22];
    float* out = (float*)d_out;

    setup_kernel<<<99, 1024>>>(x1, x2, x3, t1, b1, t2, b2, t3, b3,
                               A1_1, A1_2, A1_3, A2_1, A2_2, A2_3,
                               beta1_1, beta2_1, beta3_1);
    gemm_kernel<<<NGEMM, 512>>>(beta1_2, beta2_2, beta3_2, A4, beta4, out);
}

// round 15
// speedup vs baseline: 1.0935x; 1.0935x over previous
#include <cuda_runtime.h>
#include <cuda_bf16.h>
#include <cstdint>

#define T 1024
#define BATCH 64
#define NGEMM 192           // 3 branches * 16 tile-pairs * 4 b-quarters
#define AESZ 1112           // u16 entries per ext array (idx = 32 + (k-i))
#define AEPAD 1120          // padded stride (16B multiple)

// ---------------- device scratch (no allocations allowed) ----------------
__device__ uint2 d_g[3][BATCH][T / 2];          // (hi_word, lo_word) per k-pair
__device__ unsigned short d_ae[3][4][AEPAD];    // [0]=h0 [1]=l0 [2]=h1 [3]=l1
__device__ float d_tail[3][T];                  // (1-ba) + sig(-10)*suffix
__device__ float d_a2sm[3][T];                  // softmax(A2)
__device__ float d_Spart[3][16][BATCH];
__device__ int   d_ctr;

__device__ __forceinline__ float clamp01(float v) { return fminf(fmaxf(v, 0.f), 1.f); }
__device__ __forceinline__ unsigned short f2bf(float f) {
    return __bfloat16_as_ushort(__float2bfloat16(f));
}
__device__ __forceinline__ float bf2f(unsigned short u) {
    return __bfloat162float(__ushort_as_bfloat16(u));
}

// m16n8k16 bf16 HMMA, fp32 accum in place. Not volatile (pure-register asm).
__device__ __forceinline__ void hmma(float* d, uint32_t a0, uint32_t a1,
                                     uint32_t a2, uint32_t a3,
                                     uint32_t b0, uint32_t b1) {
    asm("mma.sync.aligned.m16n8k16.row.col.f32.bf16.bf16.f32 "
        "{%0,%1,%2,%3}, {%4,%5,%6,%7}, {%8,%9}, {%0,%1,%2,%3};"
        : "+f"(d[0]), "+f"(d[1]), "+f"(d[2]), "+f"(d[3])
        : "r"(a0), "r"(a1), "r"(a2), "r"(a3), "r"(b0), "r"(b1));
}

// ---------------------------------------------------------------------------
// Setup kernel: 99 blocks x 1024 threads.
//   blocks 0..95:  sigmoid rows -> interleaved bf16 hi/lo (2 rows per block)
//   blocks 96..98: per-branch softmax(A1)+suffix->tail, split arrays, softmax(A2)
// ---------------------------------------------------------------------------
__global__ void __launch_bounds__(1024) setup_kernel(
    const float* __restrict__ x1, const float* __restrict__ x2, const float* __restrict__ x3,
    const float* __restrict__ t1p, const float* __restrict__ b1p,
    const float* __restrict__ t2p, const float* __restrict__ b2p,
    const float* __restrict__ t3p, const float* __restrict__ b3p,
    const float* __restrict__ A1a, const float* __restrict__ A1b, const float* __restrict__ A1c,
    const float* __restrict__ A2a, const float* __restrict__ A2b, const float* __restrict__ A2c,
    const float* __restrict__ ba1, const float* __restrict__ ba2, const float* __restrict__ ba3)
{
    int bid = blockIdx.x;
    int t = threadIdx.x;

    if (bid < 96) {
        int br = bid / 32;
        int pr = bid % 32;
        const float* xs = (br == 0) ? x1 : (br == 1) ? x2 : x3;
        const float* tp = (br == 0) ? t1p : (br == 1) ? t2p : t3p;
        const float* bp = (br == 0) ? b1p : (br == 1) ? b2p : b3p;
        float tv = tp[0], bv = bp[0];

        int row = 2 * pr + (t >> 9);
        int m = t & 511;
        const float* xr = xs + row * T;
        float2 xv = *(const float2*)(xr + 2 * m);
        unsigned short h2[2], l2[2];
        float xin[2] = {xv.x, xv.y};
        #pragma unroll
        for (int e = 0; e < 2; e++) {
            float prod = __fmul_rn(xin[e], tv);   // no contraction: exact r==b test
            float r = __fsub_rn(bv, prod);
            if (r == bv) r = -10.f;
            float g = __fdividef(1.f, 1.f + __expf(-r));
            h2[e] = f2bf(g);
            l2[e] = f2bf(g - bf2f(h2[e]));
        }
        uint2 o;
        o.x = (uint32_t)h2[0] | ((uint32_t)h2[1] << 16);
        o.y = (uint32_t)l2[0] | ((uint32_t)l2[1] << 16);
        d_g[br][row][m] = o;
        return;
    }

    __shared__ float sAf[1024];
    __shared__ float sh[1024];
    __shared__ float sh32[32];
    __shared__ float swoff[32];
    int br = bid - 96;
    const float* A1 = (br == 0) ? A1a : (br == 1) ? A1b : A1c;
    const float* A2 = (br == 0) ? A2a : (br == 1) ? A2b : A2c;
    const float* bap = (br == 0) ? ba1 : (br == 1) ? ba2 : ba3;
    const float SIG10 = 4.5397868702434395e-05f;
    int w = t >> 5, l = t & 31;

    // softmax(A1)
    float v = A1[t];
    float m1 = v;
    #pragma unroll
    for (int off = 16; off; off >>= 1) m1 = fmaxf(m1, __shfl_xor_sync(0xffffffffu, m1, off));
    if (l == 0) sh32[w] = m1;
    __syncthreads();
    if (w == 0) {
        float x = sh32[l];
        #pragma unroll
        for (int off = 16; off; off >>= 1) x = fmaxf(x, __shfl_xor_sync(0xffffffffu, x, off));
        if (l == 0) sh32[0] = x;
    }
    __syncthreads();
    float M = sh32[0];
    __syncthreads();
    float e = __expf(v - M);
    float s1 = e;
    #pragma unroll
    for (int off = 16; off; off >>= 1) s1 += __shfl_xor_sync(0xffffffffu, s1, off);
    if (l == 0) sh32[w] = s1;
    __syncthreads();
    if (w == 0) {
        float x = sh32[l];
        #pragma unroll
        for (int off = 16; off; off >>= 1) x += __shfl_xor_sync(0xffffffffu, x, off);
        if (l == 0) sh32[0] = x;
    }
    __syncthreads();
    float a1 = e * __fdividef(1.f, sh32[0]);
    sAf[t] = a1;
    __syncthreads();

    // inclusive suffix scan of a1
    float s = a1;
    #pragma unroll
    for (int off = 1; off < 32; off <<= 1) {
        float o = __shfl_down_sync(0xffffffffu, s, off);
        if (l + off < 32) s += o;
    }
    if (l == 0) sh32[w] = s;
    __syncthreads();
    if (w == 0) {
        float x = sh32[l];
        float inc = x;
        #pragma unroll
        for (int off = 1; off < 32; off <<= 1) {
            float o = __shfl_down_sync(0xffffffffu, inc, off);
            if (l + off < 32) inc += o;
        }
        float excl = __shfl_down_sync(0xffffffffu, inc, 1);
        if (l == 31) excl = 0.f;
        swoff[l] = excl;
    }
    __syncthreads();
    float Ssuf_t = s + swoff[w];
    sh[t] = Ssuf_t;
    __syncthreads();
    float ba = bap[0];
    float ssuf_for_i = (t == 0) ? 0.f : sh[1024 - t];
    d_tail[br][t] = (1.f - ba) + SIG10 * ssuf_for_i;
    __syncthreads();

    // split ext arrays
    for (int x = t; x < AESZ; x += 1024) {
        float v0 = (x >= 32 && x < 1056) ? sAf[x - 32] : 0.f;
        float v1 = (x + 1 >= 32 && x + 1 < 1056) ? sAf[x - 31] : 0.f;
        unsigned short h0 = f2bf(v0);
        unsigned short h1 = f2bf(v1);
        d_ae[br][0][x] = h0;
        d_ae[br][1][x] = f2bf(v0 - bf2f(h0));
        d_ae[br][2][x] = h1;
        d_ae[br][3][x] = f2bf(v1 - bf2f(h1));
    }
    if (t < AEPAD - AESZ) {
        #pragma unroll
        for (int a = 0; a < 4; a++) d_ae[br][a][AESZ + t] = 0;
    }

    // softmax(A2)
    float v2 = A2[t];
    float m2 = v2;
    #pragma unroll
    for (int off = 16; off; off >>= 1) m2 = fmaxf(m2, __shfl_xor_sync(0xffffffffu, m2, off));
    if (l == 0) sh32[w] = m2;
    __syncthreads();
    if (w == 0) {
        float x = sh32[l];
        #pragma unroll
        for (int off = 16; off; off >>= 1) x = fmaxf(x, __shfl_xor_sync(0xffffffffu, x, off));
        if (l == 0) sh32[0] = x;
    }
    __syncthreads();
    float M2 = sh32[0];
    __syncthreads();
    float e2 = __expf(v2 - M2);
    float s2 = e2;
    #pragma unroll
    for (int off = 16; off; off >>= 1) s2 += __shfl_xor_sync(0xffffffffu, s2, off);
    if (l == 0) sh32[w] = s2;
    __syncthreads();
    if (w == 0) {
        float x = sh32[l];
        #pragma unroll
        for (int off = 16; off; off >>= 1) x += __shfl_xor_sync(0xffffffffu, x, off);
        if (l == 0) sh32[0] = x;
    }
    __syncthreads();
    d_a2sm[br][t] = e2 * __fdividef(1.f, sh32[0]);
}

// ---------------------------------------------------------------------------
// GEMM kernel: 192 CTAs x 512 threads, 2 CTAs/SM. CTA = (br, pair tp, bq).
// Register-lean mainloop: scalar prefetch regs (no indexed local array),
// A-block then B-block sequentially with fragment register reuse.
// ---------------------------------------------------------------------------
__global__ void __launch_bounds__(512, 2) gemm_kernel(
    const float* __restrict__ bb1, const float* __restrict__ bb2, const float* __restrict__ bb3,
    const float* __restrict__ A4, const float* __restrict__ beta4p,
    float* __restrict__ out)
{
    __shared__ __align__(16) unsigned short sAe[4][AEPAD];   // h0,l0,h1,l1
    __shared__ __align__(16) float sDp[8][2][32][18];
    __shared__ float sBlk[512];
    __shared__ int sDone;

    int bid = blockIdx.x;
    int br = bid >> 6;                 // 0..2
    int rem = bid & 63;
    int tp = rem >> 2;                 // pair 0..15
    int bq = rem & 3;                  // b-quarter (16 cols)
    int I0A = 32 * tp;
    int I0B = 32 * (31 - tp);
    int nk  = 64 - 2 * tp;             // k-steps from I0A to 1024
    int ksB = 2 * (31 - 2 * tp);       // first k-step overlapping tile B

    int t = threadIdx.x;
    int w = t >> 5, l = t & 31;
    int roff = l >> 2;                 // fragment row offset 0..7
    int cq = l & 3;                    // fragment k-pair 0..3
    int colg = w & 1;                  // col group (8 b each)
    int kpar = w >> 1;                 // k parity 0..7

    // ---- preamble: copy 4 split arrays (8960 B) gmem -> smem ----
    {
        const uint4* src = (const uint4*)&d_ae[br][0][0];
        uint4* dst = (uint4*)&sAe[0][0];
        const int NV = 4 * AEPAD * 2 / 16;   // 560
        for (int i = t; i < NV; i += 512) dst[i] = __ldg(src + i);
    }
    __syncthreads();

    // ---- main K loop (warp handles ks = kpar, kpar+8, ...) ----
    const uint32_t* Ah = (const uint32_t*)((roff & 1) ? sAe[2] : sAe[0]);
    const uint32_t* Al = (const uint32_t*)((roff & 1) ? sAe[3] : sAe[1]);
    int Pc = 32 + 2 * cq - roff;       // thread-constant base (u16 units)

    int n = bq * 16 + 8 * colg + roff;
    const uint2* gn = &d_g[br][n][0];

    float accA0[4] = {0, 0, 0, 0}, accA1[4] = {0, 0, 0, 0};
    float accB0[4] = {0, 0, 0, 0}, accB1[4] = {0, 0, 0, 0};

    // current B regs (scalar, no indexed array)
    uint2 b0, b1;
    {
        int kw = ((I0A + 16 * kpar) >> 1) + cq;
        b0 = __ldg(gn + kw);
        b1 = __ldg(gn + kw + 4);
    }

    for (int ks = kpar; ks < nk; ks += 8) {
        // prefetch next (distance 8 k-steps)
        uint2 p0, p1;
        bool more = (ks + 8 < nk);
        if (more) {
            int kw = ((I0A + 16 * (ks + 8)) >> 1) + cq;
            p0 = __ldg(gn + kw);
            p1 = __ldg(gn + kw + 4);
        }
        uint32_t bh0 = b0.x, bl0 = b0.y, bh1 = b1.x, bl1 = b1.y;

        // ---- A block (fragment regs live only here) ----
        {
            int Q0 = (Pc + 16 * ks) >> 1;
            uint32_t h0 = Ah[Q0 - 12], h1 = Ah[Q0 - 8], h2 = Ah[Q0 - 4];
            uint32_t h3 = Ah[Q0],      h4 = Ah[Q0 + 4];
            hmma(accA0, h3, h2, h4, h3, bh0, bh1);
            hmma(accA1, h1, h0, h2, h1, bh0, bh1);
            hmma(accA0, h3, h2, h4, h3, bl0, bl1);
            hmma(accA1, h1, h0, h2, h1, bl0, bl1);
            uint32_t g0 = Al[Q0 - 12], g1 = Al[Q0 - 8], g2 = Al[Q0 - 4];
            uint32_t g3 = Al[Q0],      g4 = Al[Q0 + 4];
            hmma(accA0, g3, g2, g4, g3, bh0, bh1);
            hmma(accA1, g1, g0, g2, g1, bh0, bh1);
        }
        // ---- B block (reuses the same fragment registers) ----
        if (ks >= ksB) {
            int QB = (Pc + 16 * (ks - ksB)) >> 1;
            uint32_t h0 = Ah[QB - 12], h1 = Ah[QB - 8], h2 = Ah[QB - 4];
            uint32_t h3 = Ah[QB],      h4 = Ah[QB + 4];
            hmma(accB0, h3, h2, h4, h3, bh0, bh1);
            hmma(accB1, h1, h0, h2, h1, bh0, bh1);
            hmma(accB0, h3, h2, h4, h3, bl0, bl1);
            hmma(accB1, h1, h0, h2, h1, bl0, bl1);
            uint32_t g0 = Al[QB - 12], g1 = Al[QB - 8], g2 = Al[QB - 4];
            uint32_t g3 = Al[QB],      g4 = Al[QB + 4];
            hmma(accB0, g3, g2, g4, g3, bh0, bh1);
            hmma(accB1, g1, g0, g2, g1, bh0, bh1);
        }

        if (more) { b0 = p0; b1 = p1; }
    }

    // ---- store per-parity partials; single barrier ----
    {
        int c0 = 8 * colg + 2 * cq;
        float (*dst)[32][18] = sDp[kpar];
        dst[0][roff +  0][c0] = accA0[0]; dst[0][roff +  0][c0 + 1] = accA0[1];
        dst[0][roff +  8][c0] = accA0[2]; dst[0][roff +  8][c0 + 1] = accA0[3];
        dst[0][roff + 16][c0] = accA1[0]; dst[0][roff + 16][c0 + 1] = accA1[1];
        dst[0][roff + 24][c0] = accA1[2]; dst[0][roff + 24][c0 + 1] = accA1[3];
        dst[1][roff +  0][c0] = accB0[0]; dst[1][roff +  0][c0 + 1] = accB0[1];
        dst[1][roff +  8][c0] = accB0[2]; dst[1][roff +  8][c0 + 1] = accB0[3];
        dst[1][roff + 16][c0] = accB1[0]; dst[1][roff + 16][c0 + 1] = accB1[1];
        dst[1][roff + 24][c0] = accB1[2]; dst[1][roff + 24][c0 + 1] = accB1[3];
    }
    __syncthreads();

    // ---- epilogue: sum 8 parities, tail, clip, A2-weight, per-b reduce ----
    {
        int b = t & 15;                // local b column 0..15
        int grp = t >> 4;              // 0..31, each handles 2 of 64 rows
        float local = 0.f;
        #pragma unroll
        for (int rr = 0; rr < 2; rr++) {
            int idx = grp * 2 + rr;    // 0..63
            int tile = idx >> 5;
            int row = idx & 31;
            int i = (tile ? I0B : I0A) + row;
            float v = 0.f;
            #pragma unroll
            for (int p = 0; p < 8; p++) v += sDp[p][tile][row][b];
            float wb1 = v + __ldg(&d_tail[br][i]);
            local += __ldg(&d_a2sm[br][i]) * (1.f - clamp01(wb1));
        }
        sBlk[t] = local;
    }
    __syncthreads();
    if (t < 16) {
        float S = 0.f;
        #pragma unroll
        for (int g = 0; g < 32; g++) S += sBlk[t + 16 * g];
        d_Spart[br][tp][bq * 16 + t] = S;
    }

    // ---- last-CTA final combine ----
    __threadfence();
    if (t == 0) {
        int v = atomicAdd(&d_ctr, 1);
        sDone = (v == NGEMM - 1) ? 1 : 0;
    }
    __syncthreads();
    if (sDone) {
        if (t < BATCH) {
            float e0 = __expf(A4[0]), e1 = __expf(A4[1]), e2 = __expf(A4[2]);
            float sinv = __fdividef(1.f, e0 + e1 + e2);
            float a40 = e0 * sinv, a41 = e1 * sinv, a42 = e2 * sinv;
            volatile float* vs = (volatile float*)d_Spart;   // [3][16][64]
            float Sb[3];
            #pragma unroll
            for (int r = 0; r < 3; r++) {
                float acc = 0.f;
                #pragma unroll
                for (int p = 0; p < 16; p++) acc += vs[(r * 16 + p) * 64 + t];
                Sb[r] = acc;
            }
            float r0 = clamp01(bb1[0] - Sb[0]);
            float r1 = clamp01(bb2[0] - Sb[1]);
            float r2 = clamp01(bb3[0] - Sb[2]);
            float acc4 = beta4p[0];
            acc4 -= a40 * (1.f - r0);
            acc4 -= a41 * (1.f - r1);
            acc4 -= a42 * (1.f - r2);
            out[t] = clamp01(acc4);
        }
        if (t == 0) d_ctr = 0;
    }
}

extern "C" void kernel_launch(void* const* d_in, const int* in_sizes, int n_in,
                              void* d_out, int out_size)
{
    const float* x1      = (const float*)d_in[0];
    const float* x2      = (const float*)d_in[1];
    const float* x3      = (const float*)d_in[2];
    const float* t1      = (const float*)d_in[3];
    const float* b1      = (const float*)d_in[4];
    const float* A1_1    = (const float*)d_in[5];
    const float* A2_1    = (const float*)d_in[6];
    const float* beta1_1 = (const float*)d_in[7];
    const float* beta1_2 = (const float*)d_in[8];
    const float* t2      = (const float*)d_in[9];
    const float* b2      = (const float*)d_in[10];
    const float* A1_2    = (const float*)d_in[11];
    const float* A2_2    = (const float*)d_in[12];
    const float* beta2_1 = (const float*)d_in[13];
    const float* beta2_2 = (const float*)d_in[14];
    const float* t3      = (const float*)d_in[15];
    const float* b3      = (const float*)d_in[16];
    const float* A1_3    = (const float*)d_in[17];
    const float* A2_3    = (const float*)d_in[18];
    const float* beta3_1 = (const float*)d_in[19];
    const float* beta3_2 = (const float*)d_in[20];
    const float* A4      = (const float*)d_in[21];
    const float* beta4   = (const float*)d_in[22];
    float* out = (float*)d_out;

    setup_kernel<<<99, 1024>>>(x1, x2, x3, t1, b1, t2, b2, t3, b3,
                               A1_1, A1_2, A1_3, A2_1, A2_2, A2_3,
                               beta1_1, beta2_1, beta3_1);
    gemm_kernel<<<NGEMM, 512>>>(beta1_2, beta2_2, beta3_2, A4, beta4, out);
}

// round 16
// speedup vs baseline: 1.1080x; 1.0133x over previous
#include <cuda_runtime.h>
#include <cuda_bf16.h>
#include <cstdint>

#define T 1024
#define BATCH 64
#define NGEMM 192           // 3 branches * 16 tile-pairs * 4 b-quarters = grid
#define AESZ 1112           // u16 entries per ext array (idx = 32 + (k-i))
#define AEPAD 1120          // padded stride (16B multiple)

// ---------------- device scratch (no allocations allowed) ----------------
__device__ uint2 d_g[3][BATCH][T / 2];          // (hi_word, lo_word) per k-pair
__device__ unsigned short d_ae[3][4][AEPAD];    // [0]=h0 [1]=l0 [2]=h1 [3]=l1
__device__ float d_tail[3][T];                  // (1-ba) + sig(-10)*suffix
__device__ float d_a2sm[3][T];                  // softmax(A2)
__device__ float d_Spart[3][16][BATCH];
__device__ int   d_bar;                         // phase barrier (reset by finisher)
__device__ int   d_ctr;                         // finisher counter (reset by finisher)

__device__ __forceinline__ float clamp01(float v) { return fminf(fmaxf(v, 0.f), 1.f); }
__device__ __forceinline__ unsigned short f2bf(float f) {
    return __bfloat16_as_ushort(__float2bfloat16(f));
}
__device__ __forceinline__ float bf2f(unsigned short u) {
    return __bfloat162float(__ushort_as_bfloat16(u));
}

// m16n8k16 bf16 HMMA, fp32 accum in place. Not volatile (pure-register asm).
__device__ __forceinline__ void hmma(float* d, uint32_t a0, uint32_t a1,
                                     uint32_t a2, uint32_t a3,
                                     uint32_t b0, uint32_t b1) {
    asm("mma.sync.aligned.m16n8k16.row.col.f32.bf16.bf16.f32 "
        "{%0,%1,%2,%3}, {%4,%5,%6,%7}, {%8,%9}, {%0,%1,%2,%3};"
        : "+f"(d[0]), "+f"(d[1]), "+f"(d[2]), "+f"(d[3])
        : "r"(a0), "r"(a1), "r"(a2), "r"(a3), "r"(b0), "r"(b1));
}

// ---------------------------------------------------------------------------
// Fused kernel: 192 CTAs x 512 threads, 2 CTAs/SM (all co-resident).
// Phase 1: sigmoid splits (1 batch row per CTA) + leader CTAs do softmaxes.
// Grid barrier. Phase 2: Toeplitz HMMA GEMM (R15 body).
// ---------------------------------------------------------------------------
__global__ void __launch_bounds__(512, 2) fused_kernel(
    const float* __restrict__ x1, const float* __restrict__ x2, const float* __restrict__ x3,
    const float* __restrict__ t1p, const float* __restrict__ b1p,
    const float* __restrict__ t2p, const float* __restrict__ b2p,
    const float* __restrict__ t3p, const float* __restrict__ b3p,
    const float* __restrict__ A1a, const float* __restrict__ A1b, const float* __restrict__ A1c,
    const float* __restrict__ A2a, const float* __restrict__ A2b, const float* __restrict__ A2c,
    const float* __restrict__ ba1, const float* __restrict__ ba2, const float* __restrict__ ba3,
    const float* __restrict__ bb1, const float* __restrict__ bb2, const float* __restrict__ bb3,
    const float* __restrict__ A4, const float* __restrict__ beta4p,
    float* __restrict__ out)
{
    __shared__ __align__(16) unsigned short sAe[4][AEPAD];   // h0,l0,h1,l1
    __shared__ __align__(16) float sDp[8][2][32][18];        // also phase-1 scratch
    __shared__ float sBlk[512];
    __shared__ float sRA[16], sRB[16], sWsum[16], sWexcl[16];
    __shared__ int sDone;

    int bid = blockIdx.x;
    int br = bid >> 6;                 // 0..2
    int rem = bid & 63;
    int tp = rem >> 2;                 // pair 0..15
    int bq = rem & 3;                  // b-quarter (16 cols)

    int t = threadIdx.x;
    int w = t >> 5, l = t & 31;

    // ================= PHASE 1: setup =================
    {
        // sigmoid splits: this CTA owns batch row `rem` of branch `br`
        const float* xs = (br == 0) ? x1 : (br == 1) ? x2 : x3;
        const float* tpp = (br == 0) ? t1p : (br == 1) ? t2p : t3p;
        const float* bpp = (br == 0) ? b1p : (br == 1) ? b2p : b3p;
        float tv = tpp[0], bv = bpp[0];
        const float* xr = xs + rem * T;
        float2 xv = *(const float2*)(xr + 2 * t);
        unsigned short h2[2], l2[2];
        float xin[2] = {xv.x, xv.y};
        #pragma unroll
        for (int e = 0; e < 2; e++) {
            float prod = __fmul_rn(xin[e], tv);   // no contraction: exact r==b test
            float r = __fsub_rn(bv, prod);
            if (r == bv) r = -10.f;
            float g = __fdividef(1.f, 1.f + __expf(-r));
            h2[e] = f2bf(g);
            l2[e] = f2bf(g - bf2f(h2[e]));
        }
        uint2 o;
        o.x = (uint32_t)h2[0] | ((uint32_t)h2[1] << 16);
        o.y = (uint32_t)l2[0] | ((uint32_t)l2[1] << 16);
        d_g[br][rem][t] = o;
    }

    if (rem == 0) {
        // ---- leader CTA: softmax(A1)+scan->tail, split arrays, softmax(A2) ----
        float* sAf  = (float*)&sDp[0][0][0][0];          // [1024]
        float* sSuf = (float*)&sDp[2][0][0][0];          // [1024]
        const float* A1 = (br == 0) ? A1a : (br == 1) ? A1b : A1c;
        const float* A2 = (br == 0) ? A2a : (br == 1) ? A2b : A2c;
        const float* bap = (br == 0) ? ba1 : (br == 1) ? ba2 : ba3;
        const float SIG10 = 4.5397868702434395e-05f;

        float2 v1 = *(const float2*)(A1 + 2 * t);
        float2 v2 = *(const float2*)(A2 + 2 * t);
        float m1 = fmaxf(v1.x, v1.y);
        float m2 = fmaxf(v2.x, v2.y);
        #pragma unroll
        for (int off = 16; off; off >>= 1) {
            m1 = fmaxf(m1, __shfl_xor_sync(0xffffffffu, m1, off));
            m2 = fmaxf(m2, __shfl_xor_sync(0xffffffffu, m2, off));
        }
        if (l == 0) { sRA[w] = m1; sRB[w] = m2; }
        __syncthreads();
        if (t == 0) {
            float a = sRA[0], b2 = sRB[0];
            #pragma unroll
            for (int k = 1; k < 16; k++) { a = fmaxf(a, sRA[k]); b2 = fmaxf(b2, sRB[k]); }
            sRA[0] = a; sRB[0] = b2;
        }
        __syncthreads();
        m1 = sRA[0]; m2 = sRB[0];
        __syncthreads();

        float e10 = __expf(v1.x - m1), e11 = __expf(v1.y - m1);
        float e20 = __expf(v2.x - m2), e21 = __expf(v2.y - m2);
        float s1 = e10 + e11, s2 = e20 + e21;
        #pragma unroll
        for (int off = 16; off; off >>= 1) {
            s1 += __shfl_xor_sync(0xffffffffu, s1, off);
            s2 += __shfl_xor_sync(0xffffffffu, s2, off);
        }
        if (l == 0) { sRA[w] = s1; sRB[w] = s2; }
        __syncthreads();
        if (t == 0) {
            float a = sRA[0], b2 = sRB[0];
            #pragma unroll
            for (int k = 1; k < 16; k++) { a += sRA[k]; b2 += sRB[k]; }
            sRA[0] = a; sRB[0] = b2;
        }
        __syncthreads();
        s1 = sRA[0]; s2 = sRB[0];
        __syncthreads();

        float inv1 = __fdividef(1.f, s1), inv2 = __fdividef(1.f, s2);
        float a0 = e10 * inv1, a1v = e11 * inv1;
        sAf[2 * t] = a0; sAf[2 * t + 1] = a1v;
        *(float2*)(&d_a2sm[br][2 * t]) = make_float2(e20 * inv2, e21 * inv2);

        // inclusive suffix scan over 2-element thread chunks
        float sn = a0 + a1v;
        float s = sn;
        #pragma unroll
        for (int off = 1; off < 32; off <<= 1) {
            float o = __shfl_down_sync(0xffffffffu, s, off);
            if (l + off < 32) s += o;
        }
        if (l == 0) sWsum[w] = s;
        __syncthreads();
        if (t < 16) {
            float tot = 0.f;
            for (int k = t + 1; k < 16; k++) tot += sWsum[k];
            sWexcl[t] = tot;
        }
        __syncthreads();
        float after = (s - sn) + sWexcl[w];
        float v1s = after + a1v;
        float v0s = v1s + a0;
        sSuf[2 * t + 1] = v1s;
        sSuf[2 * t + 0] = v0s;
        __syncthreads();

        float ba = bap[0];
        #pragma unroll
        for (int e = 0; e < 2; e++) {
            int i = 2 * t + e;
            float ssuf = (i == 0) ? 0.f : sSuf[1024 - i];
            d_tail[br][i] = (1.f - ba) + SIG10 * ssuf;
        }

        // split ext arrays
        for (int x = t; x < AESZ; x += 512) {
            float f0 = (x >= 32 && x < 1056) ? sAf[x - 32] : 0.f;
            float f1 = (x + 1 >= 32 && x + 1 < 1056) ? sAf[x - 31] : 0.f;
            unsigned short h0 = f2bf(f0);
            unsigned short h1 = f2bf(f1);
            d_ae[br][0][x] = h0;
            d_ae[br][1][x] = f2bf(f0 - bf2f(h0));
            d_ae[br][2][x] = h1;
            d_ae[br][3][x] = f2bf(f1 - bf2f(h1));
        }
        if (t < AEPAD - AESZ) {
            #pragma unroll
            for (int a = 0; a < 4; a++) d_ae[br][a][AESZ + t] = 0;
        }
    }

    // ================= GRID BARRIER =================
    __threadfence();
    __syncthreads();
    if (t == 0) {
        atomicAdd(&d_bar, 1);
        while (*(volatile int*)&d_bar < NGEMM) { }
    }
    __syncthreads();

    // ================= PHASE 2: GEMM (R15 body) =================
    int I0A = 32 * tp;
    int I0B = 32 * (31 - tp);
    int nk  = 64 - 2 * tp;
    int ksB = 2 * (31 - 2 * tp);

    int roff = l >> 2;                 // fragment row offset 0..7
    int cq = l & 3;                    // fragment k-pair 0..3
    int colg = w & 1;                  // col group (8 b each)
    int kpar = w >> 1;                 // k parity 0..7

    // copy 4 split arrays gmem -> smem
    {
        const uint4* src = (const uint4*)&d_ae[br][0][0];
        uint4* dst = (uint4*)&sAe[0][0];
        const int NV = 4 * AEPAD * 2 / 16;   // 560
        for (int i = t; i < NV; i += 512) dst[i] = __ldg(src + i);
    }
    __syncthreads();

    const uint32_t* Ah = (const uint32_t*)((roff & 1) ? sAe[2] : sAe[0]);
    const uint32_t* Al = (const uint32_t*)((roff & 1) ? sAe[3] : sAe[1]);
    int Pc = 32 + 2 * cq - roff;

    int n = bq * 16 + 8 * colg + roff;
    const uint2* gn = &d_g[br][n][0];

    float accA0[4] = {0, 0, 0, 0}, accA1[4] = {0, 0, 0, 0};
    float accB0[4] = {0, 0, 0, 0}, accB1[4] = {0, 0, 0, 0};

    uint2 b0, b1;
    {
        int kw = ((I0A + 16 * kpar) >> 1) + cq;
        b0 = __ldg(gn + kw);
        b1 = __ldg(gn + kw + 4);
    }

    for (int ks = kpar; ks < nk; ks += 8) {
        uint2 p0, p1;
        bool more = (ks + 8 < nk);
        if (more) {
            int kw = ((I0A + 16 * (ks + 8)) >> 1) + cq;
            p0 = __ldg(gn + kw);
            p1 = __ldg(gn + kw + 4);
        }
        uint32_t bh0 = b0.x, bl0 = b0.y, bh1 = b1.x, bl1 = b1.y;

        {
            int Q0 = (Pc + 16 * ks) >> 1;
            uint32_t h0 = Ah[Q0 - 12], h1 = Ah[Q0 - 8], h2 = Ah[Q0 - 4];
            uint32_t h3 = Ah[Q0],      h4 = Ah[Q0 + 4];
            hmma(accA0, h3, h2, h4, h3, bh0, bh1);
            hmma(accA1, h1, h0, h2, h1, bh0, bh1);
            hmma(accA0, h3, h2, h4, h3, bl0, bl1);
            hmma(accA1, h1, h0, h2, h1, bl0, bl1);
            uint32_t g0 = Al[Q0 - 12], g1 = Al[Q0 - 8], g2 = Al[Q0 - 4];
            uint32_t g3 = Al[Q0],      g4 = Al[Q0 + 4];
            hmma(accA0, g3, g2, g4, g3, bh0, bh1);
            hmma(accA1, g1, g0, g2, g1, bh0, bh1);
        }
        if (ks >= ksB) {
            int QB = (Pc + 16 * (ks - ksB)) >> 1;
            uint32_t h0 = Ah[QB - 12], h1 = Ah[QB - 8], h2 = Ah[QB - 4];
            uint32_t h3 = Ah[QB],      h4 = Ah[QB + 4];
            hmma(accB0, h3, h2, h4, h3, bh0, bh1);
            hmma(accB1, h1, h0, h2, h1, bh0, bh1);
            hmma(accB0, h3, h2, h4, h3, bl0, bl1);
            hmma(accB1, h1, h0, h2, h1, bl0, bl1);
            uint32_t g0 = Al[QB - 12], g1 = Al[QB - 8], g2 = Al[QB - 4];
            uint32_t g3 = Al[QB],      g4 = Al[QB + 4];
            hmma(accB0, g3, g2, g4, g3, bh0, bh1);
            hmma(accB1, g1, g0, g2, g1, bh0, bh1);
        }

        if (more) { b0 = p0; b1 = p1; }
    }

    // store per-parity partials; single barrier
    __syncthreads();   // protect sDp (leader used it as scratch; all passed barrier already)
    {
        int c0 = 8 * colg + 2 * cq;
        float (*dst)[32][18] = sDp[kpar];
        dst[0][roff +  0][c0] = accA0[0]; dst[0][roff +  0][c0 + 1] = accA0[1];
        dst[0][roff +  8][c0] = accA0[2]; dst[0][roff +  8][c0 + 1] = accA0[3];
        dst[0][roff + 16][c0] = accA1[0]; dst[0][roff + 16][c0 + 1] = accA1[1];
        dst[0][roff + 24][c0] = accA1[2]; dst[0][roff + 24][c0 + 1] = accA1[3];
        dst[1][roff +  0][c0] = accB0[0]; dst[1][roff +  0][c0 + 1] = accB0[1];
        dst[1][roff +  8][c0] = accB0[2]; dst[1][roff +  8][c0 + 1] = accB0[3];
        dst[1][roff + 16][c0] = accB1[0]; dst[1][roff + 16][c0 + 1] = accB1[1];
        dst[1][roff + 24][c0] = accB1[2]; dst[1][roff + 24][c0 + 1] = accB1[3];
    }
    __syncthreads();

    // epilogue: sum 8 parities, tail, clip, A2-weight, per-b reduce
    {
        int b = t & 15;
        int grp = t >> 4;
        float local = 0.f;
        #pragma unroll
        for (int rr = 0; rr < 2; rr++) {
            int idx = grp * 2 + rr;
            int tile = idx >> 5;
            int row = idx & 31;
            int i = (tile ? I0B : I0A) + row;
            float v = 0.f;
            #pragma unroll
            for (int p = 0; p < 8; p++) v += sDp[p][tile][row][b];
            float wb1 = v + __ldg(&d_tail[br][i]);
            local += __ldg(&d_a2sm[br][i]) * (1.f - clamp01(wb1));
        }
        sBlk[t] = local;
    }
    __syncthreads();
    if (t < 16) {
        float S = 0.f;
        #pragma unroll
        for (int g = 0; g < 32; g++) S += sBlk[t + 16 * g];
        d_Spart[br][tp][bq * 16 + t] = S;
    }

    // last-CTA final combine
    __threadfence();
    if (t == 0) {
        int v = atomicAdd(&d_ctr, 1);
        sDone = (v == NGEMM - 1) ? 1 : 0;
    }
    __syncthreads();
    if (sDone) {
        if (t < BATCH) {
            float e0 = __expf(A4[0]), e1 = __expf(A4[1]), e2 = __expf(A4[2]);
            float sinv = __fdividef(1.f, e0 + e1 + e2);
            float a40 = e0 * sinv, a41 = e1 * sinv, a42 = e2 * sinv;
            volatile float* vs = (volatile float*)d_Spart;   // [3][16][64]
            float Sb[3];
            #pragma unroll
            for (int r = 0; r < 3; r++) {
                float acc = 0.f;
                #pragma unroll
                for (int p = 0; p < 16; p++) acc += vs[(r * 16 + p) * 64 + t];
                Sb[r] = acc;
            }
            float r0 = clamp01(bb1[0] - Sb[0]);
            float r1 = clamp01(bb2[0] - Sb[1]);
            float r2 = clamp01(bb3[0] - Sb[2]);
            float acc4 = beta4p[0];
            acc4 -= a40 * (1.f - r0);
            acc4 -= a41 * (1.f - r1);
            acc4 -= a42 * (1.f - r2);
            out[t] = clamp01(acc4);
        }
        if (t == 0) { d_ctr = 0; d_bar = 0; }   // reset for next graph replay
    }
}

extern "C" void kernel_launch(void* const* d_in, const int* in_sizes, int n_in,
                              void* d_out, int out_size)
{
    const float* x1      = (const float*)d_in[0];
    const float* x2      = (const float*)d_in[1];
    const float* x3      = (const float*)d_in[2];
    const float* t1      = (const float*)d_in[3];
    const float* b1      = (const float*)d_in[4];
    const float* A1_1    = (const float*)d_in[5];
    const float* A2_1    = (const float*)d_in[6];
    const float* beta1_1 = (const float*)d_in[7];
    const float* beta1_2 = (const float*)d_in[8];
    const float* t2      = (const float*)d_in[9];
    const float* b2      = (const float*)d_in[10];
    const float* A1_2    = (const float*)d_in[11];
    const float* A2_2    = (const float*)d_in[12];
    const float* beta2_1 = (const float*)d_in[13];
    const float* beta2_2 = (const float*)d_in[14];
    const float* t3      = (const float*)d_in[15];
    const float* b3      = (const float*)d_in[16];
    const float* A1_3    = (const float*)d_in[17];
    const float* A2_3    = (const float*)d_in[18];
    const float* beta3_1 = (const float*)d_in[19];
    const float* beta3_2 = (const float*)d_in[20];
    const float* A4      = (const float*)d_in[21];
    const float* beta4   = (const float*)d_in[22];
    float* out = (float*)d_out;

    fused_kernel<<<NGEMM, 512>>>(x1, x2, x3, t1, b1, t2, b2, t3, b3,
                                 A1_1, A1_2, A1_3, A2_1, A2_2, A2_3,
                                 beta1_1, beta2_1, beta3_1,
                                 beta1_2, beta2_2, beta3_2,
                                 A4, beta4, out);
}